// round 1
// baseline (speedup 1.0000x reference)
#include <cuda_runtime.h>
#include <cuda_bf16.h>
#include <math.h>

#define Nn 20000
#define Ee 40000
#define Bb 1000
#define Ff 32
#define Dd 64
#define HE 128
#define DDm 4096

// ---------------- scratch (static device allocations, allowed) ----------------
__device__ float g_h[Nn * Dd];                       // node state (out == h)
__device__ float g_H[Ee * HE];                       // edge hidden [E,128]
__device__ __nv_bfloat16 g_We[(size_t)Ee * DDm];     // edge weights [E,64,64] bf16 (327MB)
__device__ float g_agg[Nn * Dd];
__device__ float g_deg[Nn];
__device__ float g_e[Nn];
__device__ float g_qstar[Bb * 2 * Dd];
__device__ float g_hl[Bb * Dd];
__device__ float g_cl[Bb * Dd];
__device__ int   g_seg[Bb + 1];

__device__ __forceinline__ float sigf(float v) { return 1.0f / (1.0f + expf(-v)); }

// ---------------- lin0: h = relu(x @ W0^T + b0) ----------------
__global__ void k_lin0(const float* __restrict__ x, const float* __restrict__ W0,
                       const float* __restrict__ b0) {
    int n = blockIdx.x, t = threadIdx.x;
    __shared__ float sx[Ff];
    if (t < Ff) sx[t] = x[n * Ff + t];
    __syncthreads();
    float acc = b0[t];
    const float4* wp = (const float4*)&W0[t * Ff];
#pragma unroll
    for (int q = 0; q < Ff / 4; q++) {
        float4 w = wp[q];
        float4 v = *(const float4*)&sx[q * 4];
        acc += v.x * w.x + v.y * w.y + v.z * w.z + v.w * w.w;
    }
    g_h[n * Dd + t] = fmaxf(acc, 0.0f);
}

// ---------------- edge hidden: H = relu(ea @ We1^T + be1) ----------------
__global__ void k_edgeh(const float* __restrict__ ea, const float* __restrict__ We1,
                        const float* __restrict__ be1) {
    int e = blockIdx.x, k = threadIdx.x;
    __shared__ float sa[5];
    if (k < 5) sa[k] = ea[e * 5 + k];
    __syncthreads();
    float acc = be1[k];
#pragma unroll
    for (int j = 0; j < 5; j++) acc += sa[j] * We1[k * 5 + j];
    g_H[e * HE + k] = fmaxf(acc, 0.0f);
}

// ---------------- big GEMM: We[e,m] = H[e,:] . We2[m,:] + be2[m]  (bf16 out) ----------------
// A = g_H [40000,128] row-major, B = We2 [4096,128] row-major (NT gemm), K=128.
#define BM 128
#define BN 128
#define BK 16
__global__ void __launch_bounds__(256) k_gemm(const float* __restrict__ We2,
                                              const float* __restrict__ be2) {
    __shared__ float As[BK][BM + 4];
    __shared__ float Bs[BK][BN + 4];
    int row0 = blockIdx.x * BM;
    int col0 = blockIdx.y * BN;
    int tid = threadIdx.x;
    int tx = tid & 15, ty = tid >> 4;
    float acc[8][8];
#pragma unroll
    for (int i = 0; i < 8; i++)
#pragma unroll
        for (int j = 0; j < 8; j++) acc[i][j] = 0.0f;

    for (int kc = 0; kc < HE; kc += BK) {
#pragma unroll
        for (int it = 0; it < 2; it++) {
            int idx = tid + it * 256;          // 0..511
            int r = idx >> 2;                  // 0..127
            int kq = (idx & 3) * 4;            // 0,4,8,12
            int grow = row0 + r;
            float4 v = make_float4(0.f, 0.f, 0.f, 0.f);
            if (grow < Ee) v = *(const float4*)&g_H[(size_t)grow * HE + kc + kq];
            As[kq + 0][r] = v.x; As[kq + 1][r] = v.y; As[kq + 2][r] = v.z; As[kq + 3][r] = v.w;
            float4 w = *(const float4*)&We2[(size_t)(col0 + r) * HE + kc + kq];
            Bs[kq + 0][r] = w.x; Bs[kq + 1][r] = w.y; Bs[kq + 2][r] = w.z; Bs[kq + 3][r] = w.w;
        }
        __syncthreads();
#pragma unroll
        for (int k = 0; k < BK; k++) {
            float4 a0 = *(const float4*)&As[k][ty * 8];
            float4 a1 = *(const float4*)&As[k][ty * 8 + 4];
            float4 b0 = *(const float4*)&Bs[k][tx * 8];
            float4 b1 = *(const float4*)&Bs[k][tx * 8 + 4];
            float a[8] = {a0.x, a0.y, a0.z, a0.w, a1.x, a1.y, a1.z, a1.w};
            float b[8] = {b0.x, b0.y, b0.z, b0.w, b1.x, b1.y, b1.z, b1.w};
#pragma unroll
            for (int i = 0; i < 8; i++)
#pragma unroll
                for (int j = 0; j < 8; j++) acc[i][j] += a[i] * b[j];
        }
        __syncthreads();
    }
    // epilogue: + be2, convert to bf16
    float bb[8];
#pragma unroll
    for (int j = 0; j < 8; j++) bb[j] = be2[col0 + tx * 8 + j];
#pragma unroll
    for (int i = 0; i < 8; i++) {
        int grow = row0 + ty * 8 + i;
        if (grow >= Ee) continue;
        __nv_bfloat162* op = (__nv_bfloat162*)(g_We + (size_t)grow * DDm + col0 + tx * 8);
#pragma unroll
        for (int j = 0; j < 4; j++) {
            float2 c = make_float2(acc[i][2 * j] + bb[2 * j], acc[i][2 * j + 1] + bb[2 * j + 1]);
            op[j] = __float22bfloat162_rn(c);
        }
    }
}

// ---------------- degree ----------------
__global__ void k_zero_deg() {
    int i = blockIdx.x * blockDim.x + threadIdx.x;
    if (i < Nn) g_deg[i] = 0.0f;
}
__global__ void k_count(const int* __restrict__ ei) {
    int e = blockIdx.x * blockDim.x + threadIdx.x;
    if (e < Ee) atomicAdd(&g_deg[ei[Ee + e]], 1.0f);
}

// ---------------- segment starts (batch is sorted) ----------------
__global__ void k_segstart(const int* __restrict__ batch) {
    int b = blockIdx.x * blockDim.x + threadIdx.x;
    if (b > Bb) return;
    int lo = 0, hi = Nn;
    while (lo < hi) {
        int mid = (lo + hi) >> 1;
        if (batch[mid] < b) lo = mid + 1; else hi = mid;
    }
    g_seg[b] = lo;
}

// ---------------- message + scatter ----------------
__global__ void k_zero_agg() {
    int i = blockIdx.x * blockDim.x + threadIdx.x;
    if (i < Nn * Dd) g_agg[i] = 0.0f;
}
__global__ void k_msg(const int* __restrict__ ei) {
    int w = threadIdx.x >> 5;
    int e = blockIdx.x * 8 + w;
    int lane = threadIdx.x & 31;
    __shared__ float ss[8][Dd];
    if (e >= Ee) return;
    int src = ei[e], dst = ei[Ee + e];
    ss[w][lane] = g_h[src * Dd + lane];
    ss[w][lane + 32] = g_h[src * Dd + 32 + lane];
    __syncwarp();
    const __nv_bfloat162* W = (const __nv_bfloat162*)(g_We + (size_t)e * DDm);
    float a0 = 0.f, a1 = 0.f;
#pragma unroll
    for (int i = 0; i < Dd; i++) {
        float si = ss[w][i];
        float2 wf = __bfloat1622float2(W[i * 32 + lane]);
        a0 += si * wf.x;
        a1 += si * wf.y;
    }
    atomicAdd(&g_agg[dst * Dd + 2 * lane], a0);
    atomicAdd(&g_agg[dst * Dd + 2 * lane + 1], a1);
}

// ---------------- GRU cell ----------------
__global__ void k_gru(const float* __restrict__ W_ih, const float* __restrict__ W_hh,
                      const float* __restrict__ b_ih, const float* __restrict__ b_hh,
                      const float* __restrict__ b_conv) {
    int n = blockIdx.x, t = threadIdx.x;
    __shared__ float sm[Dd], sh[Dd];
    float dg = fmaxf(g_deg[n], 1.0f);
    sm[t] = fmaxf(g_agg[n * Dd + t] / dg + b_conv[t], 0.0f);
    sh[t] = g_h[n * Dd + t];
    __syncthreads();
    float gir = b_ih[t], giz = b_ih[Dd + t], gin = b_ih[2 * Dd + t];
    float ghr = b_hh[t], ghz = b_hh[Dd + t], ghn = b_hh[2 * Dd + t];
    const float4* Wr = (const float4*)&W_ih[t * Dd];
    const float4* Wz = (const float4*)&W_ih[(Dd + t) * Dd];
    const float4* Wn = (const float4*)&W_ih[(2 * Dd + t) * Dd];
    const float4* Vr = (const float4*)&W_hh[t * Dd];
    const float4* Vz = (const float4*)&W_hh[(Dd + t) * Dd];
    const float4* Vn = (const float4*)&W_hh[(2 * Dd + t) * Dd];
#pragma unroll
    for (int q = 0; q < Dd / 4; q++) {
        float4 m4 = *(const float4*)&sm[q * 4];
        float4 h4 = *(const float4*)&sh[q * 4];
        float4 w;
        w = Wr[q]; gir += m4.x * w.x + m4.y * w.y + m4.z * w.z + m4.w * w.w;
        w = Wz[q]; giz += m4.x * w.x + m4.y * w.y + m4.z * w.z + m4.w * w.w;
        w = Wn[q]; gin += m4.x * w.x + m4.y * w.y + m4.z * w.z + m4.w * w.w;
        w = Vr[q]; ghr += h4.x * w.x + h4.y * w.y + h4.z * w.z + h4.w * w.w;
        w = Vz[q]; ghz += h4.x * w.x + h4.y * w.y + h4.z * w.z + h4.w * w.w;
        w = Vn[q]; ghn += h4.x * w.x + h4.y * w.y + h4.z * w.z + h4.w * w.w;
    }
    float r = sigf(gir + ghr);
    float z = sigf(giz + ghz);
    float nn = tanhf(gin + r * ghn);
    g_h[n * Dd + t] = (1.0f - z) * nn + z * sh[t];
}

// ---------------- Set2Set ----------------
__global__ void k_zero_s2s() {
    int i = blockIdx.x * blockDim.x + threadIdx.x;
    if (i < Bb * 128) g_qstar[i] = 0.0f;
    else if (i < Bb * 192) g_hl[i - Bb * 128] = 0.0f;
    else if (i < Bb * 256) g_cl[i - Bb * 192] = 0.0f;
}

__global__ void k_lstm(const float* __restrict__ W_ihl, const float* __restrict__ W_hhl,
                       const float* __restrict__ b_ihl, const float* __restrict__ b_hhl) {
    int b = blockIdx.x, t = threadIdx.x;
    __shared__ float sq[2 * Dd], shl[Dd];
    sq[t] = g_qstar[b * 2 * Dd + t];
    sq[Dd + t] = g_qstar[b * 2 * Dd + Dd + t];
    shl[t] = g_hl[b * Dd + t];
    __syncthreads();
    float gi = b_ihl[t] + b_hhl[t];
    float gf = b_ihl[Dd + t] + b_hhl[Dd + t];
    float gg = b_ihl[2 * Dd + t] + b_hhl[2 * Dd + t];
    float go = b_ihl[3 * Dd + t] + b_hhl[3 * Dd + t];
    const float4* Pi = (const float4*)&W_ihl[t * 128];
    const float4* Pf = (const float4*)&W_ihl[(Dd + t) * 128];
    const float4* Pg = (const float4*)&W_ihl[(2 * Dd + t) * 128];
    const float4* Po = (const float4*)&W_ihl[(3 * Dd + t) * 128];
#pragma unroll
    for (int q = 0; q < 32; q++) {
        float4 v = *(const float4*)&sq[q * 4];
        float4 w;
        w = Pi[q]; gi += v.x * w.x + v.y * w.y + v.z * w.z + v.w * w.w;
        w = Pf[q]; gf += v.x * w.x + v.y * w.y + v.z * w.z + v.w * w.w;
        w = Pg[q]; gg += v.x * w.x + v.y * w.y + v.z * w.z + v.w * w.w;
        w = Po[q]; go += v.x * w.x + v.y * w.y + v.z * w.z + v.w * w.w;
    }
    const float4* Hi = (const float4*)&W_hhl[t * Dd];
    const float4* Hf = (const float4*)&W_hhl[(Dd + t) * Dd];
    const float4* Hg = (const float4*)&W_hhl[(2 * Dd + t) * Dd];
    const float4* Ho = (const float4*)&W_hhl[(3 * Dd + t) * Dd];
#pragma unroll
    for (int q = 0; q < 16; q++) {
        float4 v = *(const float4*)&shl[q * 4];
        float4 w;
        w = Hi[q]; gi += v.x * w.x + v.y * w.y + v.z * w.z + v.w * w.w;
        w = Hf[q]; gf += v.x * w.x + v.y * w.y + v.z * w.z + v.w * w.w;
        w = Hg[q]; gg += v.x * w.x + v.y * w.y + v.z * w.z + v.w * w.w;
        w = Ho[q]; go += v.x * w.x + v.y * w.y + v.z * w.z + v.w * w.w;
    }
    float c = g_cl[b * Dd + t];
    c = sigf(gf) * c + sigf(gi) * tanhf(gg);
    float hl = sigf(go) * tanhf(c);
    g_cl[b * Dd + t] = c;
    g_hl[b * Dd + t] = hl;
}

__global__ void k_dot(const int* __restrict__ batch) {
    int w = threadIdx.x >> 5;
    int n = blockIdx.x * 8 + w;
    int lane = threadIdx.x & 31;
    if (n >= Nn) return;
    int b = batch[n];
    float v = g_h[n * Dd + lane] * g_hl[b * Dd + lane]
            + g_h[n * Dd + 32 + lane] * g_hl[b * Dd + 32 + lane];
#pragma unroll
    for (int off = 16; off > 0; off >>= 1) v += __shfl_down_sync(0xffffffff, v, off);
    if (lane == 0) g_e[n] = v;
}

__global__ void k_attn() {
    int b = blockIdx.x, t = threadIdx.x;
    int s = g_seg[b], en = g_seg[b + 1];
    __shared__ float red[Dd];
    float mx = -1e30f;
    for (int n = s + t; n < en; n += Dd) mx = fmaxf(mx, g_e[n]);
    red[t] = mx;
    __syncthreads();
    for (int o = 32; o > 0; o >>= 1) {
        if (t < o) red[t] = fmaxf(red[t], red[t + o]);
        __syncthreads();
    }
    float emax = red[0];
    float racc = 0.f, wsum = 0.f;
    for (int n = s; n < en; n++) {
        float wv = expf(g_e[n] - emax);
        wsum += wv;
        racc += wv * g_h[n * Dd + t];
    }
    float r = (en > s) ? (racc / wsum) : 0.0f;
    g_qstar[b * 2 * Dd + t] = g_hl[b * Dd + t];
    g_qstar[b * 2 * Dd + Dd + t] = r;
}

// ---------------- output MLP ----------------
__global__ void k_mlp(const float* __restrict__ W1, const float* __restrict__ b1,
                      const float* __restrict__ W2, const float* __restrict__ b2,
                      float* __restrict__ pred) {
    int b = blockIdx.x, t = threadIdx.x;
    __shared__ float sq[2 * Dd];
    __shared__ float red[Dd];
    sq[t] = g_qstar[b * 2 * Dd + t];
    sq[Dd + t] = g_qstar[b * 2 * Dd + Dd + t];
    __syncthreads();
    float acc = b1[t];
    const float4* Wp = (const float4*)&W1[t * 128];
#pragma unroll
    for (int q = 0; q < 32; q++) {
        float4 w = Wp[q];
        float4 v = *(const float4*)&sq[q * 4];
        acc += v.x * w.x + v.y * w.y + v.z * w.z + v.w * w.w;
    }
    float y = fmaxf(acc, 0.0f);
    red[t] = y * W2[t];
    __syncthreads();
    for (int o = 32; o > 0; o >>= 1) {
        if (t < o) red[t] += red[t + o];
        __syncthreads();
    }
    if (t == 0) pred[b] = red[0] + b2[0];
}

// ---------------- launch ----------------
extern "C" void kernel_launch(void* const* d_in, const int* in_sizes, int n_in,
                              void* d_out, int out_size) {
    const float* x      = (const float*)d_in[0];
    const float* ea     = (const float*)d_in[1];
    const int*   ei     = (const int*)d_in[2];
    const int*   batch  = (const int*)d_in[3];
    const float* W0     = (const float*)d_in[4];
    const float* b0     = (const float*)d_in[5];
    const float* We1    = (const float*)d_in[6];
    const float* be1    = (const float*)d_in[7];
    const float* We2    = (const float*)d_in[8];
    const float* be2    = (const float*)d_in[9];
    const float* b_conv = (const float*)d_in[10];
    const float* W_ih   = (const float*)d_in[11];
    const float* W_hh   = (const float*)d_in[12];
    const float* b_ih   = (const float*)d_in[13];
    const float* b_hh   = (const float*)d_in[14];
    const float* W_ihl  = (const float*)d_in[15];
    const float* W_hhl  = (const float*)d_in[16];
    const float* b_ihl  = (const float*)d_in[17];
    const float* b_hhl  = (const float*)d_in[18];
    const float* W1     = (const float*)d_in[19];
    const float* b1     = (const float*)d_in[20];
    const float* W2     = (const float*)d_in[21];
    const float* b2     = (const float*)d_in[22];
    float* pred = (float*)d_out;

    k_lin0<<<Nn, Dd>>>(x, W0, b0);
    k_edgeh<<<Ee, HE>>>(ea, We1, be1);
    dim3 gg((Ee + BM - 1) / BM, DDm / BN);
    k_gemm<<<gg, 256>>>(We2, be2);
    k_zero_deg<<<(Nn + 255) / 256, 256>>>();
    k_count<<<(Ee + 255) / 256, 256>>>(ei);
    k_segstart<<<(Bb + 1 + 127) / 128, 128>>>(batch);

    for (int it = 0; it < 3; it++) {
        k_zero_agg<<<(Nn * Dd + 255) / 256, 256>>>();
        k_msg<<<(Ee + 7) / 8, 256>>>(ei);
        k_gru<<<Nn, Dd>>>(W_ih, W_hh, b_ih, b_hh, b_conv);
    }

    k_zero_s2s<<<(Bb * 256 + 255) / 256, 256>>>();
    for (int it = 0; it < 3; it++) {
        k_lstm<<<Bb, Dd>>>(W_ihl, W_hhl, b_ihl, b_hhl);
        k_dot<<<(Nn + 7) / 8, 256>>>(batch);
        k_attn<<<Bb, Dd>>>();
    }
    k_mlp<<<Bb, Dd>>>(W1, b1, W2, b2, pred);
}

// round 3
// speedup vs baseline: 1.3381x; 1.3381x over previous
#include <cuda_runtime.h>
#include <cuda_bf16.h>
#include <math.h>
#include <stdint.h>

#define Nn 20000
#define Ee 40000
#define Bb 1000
#define Ff 32
#define Dd 64
#define HE 128
#define DDm 4096

// ---------------- scratch ----------------
__device__ float g_h[Nn * Dd];                       // node state
__device__ __nv_bfloat16 g_Hb[(size_t)Ee * HE];      // edge hidden bf16 [E,128]
__device__ __nv_bfloat16 g_Wb[DDm * HE];             // We2 bf16 [4096,128]
__device__ __nv_bfloat16 g_We[(size_t)Ee * DDm];     // edge weights bf16 (327MB)
__device__ float g_agg[Nn * Dd];
__device__ float g_deg[Nn];
__device__ float g_e[Nn];
__device__ float g_qstar[Bb * 2 * Dd];
__device__ float g_hl[Bb * Dd];
__device__ float g_cl[Bb * Dd];
__device__ int   g_seg[Bb + 1];

__device__ __forceinline__ float sigf(float v) { return 1.0f / (1.0f + expf(-v)); }

// ---------------- lin0 ----------------
__global__ void k_lin0(const float* __restrict__ x, const float* __restrict__ W0,
                       const float* __restrict__ b0) {
    int n = blockIdx.x, t = threadIdx.x;
    __shared__ float sx[Ff];
    if (t < Ff) sx[t] = x[n * Ff + t];
    __syncthreads();
    float acc = b0[t];
    const float4* wp = (const float4*)&W0[t * Ff];
#pragma unroll
    for (int q = 0; q < Ff / 4; q++) {
        float4 w = wp[q];
        float4 v = *(const float4*)&sx[q * 4];
        acc += v.x * w.x + v.y * w.y + v.z * w.z + v.w * w.w;
    }
    g_h[n * Dd + t] = fmaxf(acc, 0.0f);
}

// ---------------- edge hidden (bf16 out) ----------------
__global__ void k_edgeh(const float* __restrict__ ea, const float* __restrict__ We1,
                        const float* __restrict__ be1) {
    int e = blockIdx.x, k = threadIdx.x;
    __shared__ float sa[5];
    if (k < 5) sa[k] = ea[e * 5 + k];
    __syncthreads();
    float acc = be1[k];
#pragma unroll
    for (int j = 0; j < 5; j++) acc += sa[j] * We1[k * 5 + j];
    g_Hb[(size_t)e * HE + k] = __float2bfloat16(fmaxf(acc, 0.0f));
}

// ---------------- We2 -> bf16 ----------------
__global__ void k_cvtW(const float* __restrict__ We2) {
    int i = blockIdx.x * blockDim.x + threadIdx.x;
    if (i < DDm * HE) g_Wb[i] = __float2bfloat16(We2[i]);
}

// ---------------- tensor-core GEMM: We = Hb @ Wb^T + be2 (bf16 out) ----------------
// A [E,128] bf16 row-major (K contiguous), B [4096,128] bf16 row-major (NT).
#define SPAD 136   // row stride in bf16 (272B), conflict-free ldmatrix
__global__ void __launch_bounds__(256) k_gemm_tc(const float* __restrict__ be2) {
    extern __shared__ __nv_bfloat16 smem[];
    __nv_bfloat16* As = smem;                 // [128][SPAD]
    __nv_bfloat16* Bs = smem + 128 * SPAD;    // [128][SPAD]
    int row0 = blockIdx.x * 128;
    int col0 = blockIdx.y * 128;
    int tid = threadIdx.x;

    // load tiles (uint4 = 8 bf16)
    for (int idx = tid; idx < 2048; idx += 256) {
        int r = idx >> 4, c = (idx & 15) * 8;
        uint4 v = make_uint4(0u, 0u, 0u, 0u);
        if (row0 + r < Ee) v = *(const uint4*)&g_Hb[(size_t)(row0 + r) * HE + c];
        *(uint4*)&As[r * SPAD + c] = v;
        uint4 w = *(const uint4*)&g_Wb[(size_t)(col0 + r) * HE + c];
        *(uint4*)&Bs[r * SPAD + c] = w;
    }
    __syncthreads();

    int wid = tid >> 5, lane = tid & 31;
    int wm = (wid >> 2) * 64;   // warp M offset: 0/64
    int wn = (wid & 3) * 32;    // warp N offset: 0/32/64/96
    int q = lane >> 3, r8 = lane & 7;

    float acc[4][4][4];
#pragma unroll
    for (int i = 0; i < 4; i++)
#pragma unroll
        for (int j = 0; j < 4; j++)
#pragma unroll
            for (int c = 0; c < 4; c++) acc[i][j][c] = 0.0f;

#pragma unroll
    for (int k0 = 0; k0 < 128; k0 += 16) {
        uint32_t a[4][4];
        uint32_t b[4][2];
        // A fragments: 4 m16k16 tiles
#pragma unroll
        for (int mi = 0; mi < 4; mi++) {
            int m = wm + mi * 16 + ((q & 1) * 8) + r8;
            int k = k0 + ((q >> 1) * 8);
            uint32_t addr = (uint32_t)__cvta_generic_to_shared(&As[m * SPAD + k]);
            asm volatile("ldmatrix.sync.aligned.m8n8.x4.shared.b16 {%0,%1,%2,%3}, [%4];"
                         : "=r"(a[mi][0]), "=r"(a[mi][1]), "=r"(a[mi][2]), "=r"(a[mi][3])
                         : "r"(addr));
        }
        // B fragments: 4 n8k16 tiles via 2x ldmatrix.x4 (each covers 16 n-rows)
#pragma unroll
        for (int np = 0; np < 2; np++) {
            int n = wn + np * 16 + ((q >> 1) * 8) + r8;   // FIXED: np*16 (was np*32)
            int k = k0 + ((q & 1) * 8);
            uint32_t addr = (uint32_t)__cvta_generic_to_shared(&Bs[n * SPAD + k]);
            asm volatile("ldmatrix.sync.aligned.m8n8.x4.shared.b16 {%0,%1,%2,%3}, [%4];"
                         : "=r"(b[np * 2][0]), "=r"(b[np * 2][1]),
                           "=r"(b[np * 2 + 1][0]), "=r"(b[np * 2 + 1][1])
                         : "r"(addr));
        }
#pragma unroll
        for (int mi = 0; mi < 4; mi++)
#pragma unroll
            for (int ni = 0; ni < 4; ni++) {
                asm volatile(
                    "mma.sync.aligned.m16n8k16.row.col.f32.bf16.bf16.f32 "
                    "{%0,%1,%2,%3}, {%4,%5,%6,%7}, {%8,%9}, {%0,%1,%2,%3};"
                    : "+f"(acc[mi][ni][0]), "+f"(acc[mi][ni][1]),
                      "+f"(acc[mi][ni][2]), "+f"(acc[mi][ni][3])
                    : "r"(a[mi][0]), "r"(a[mi][1]), "r"(a[mi][2]), "r"(a[mi][3]),
                      "r"(b[ni][0]), "r"(b[ni][1]));
            }
    }

    // epilogue
#pragma unroll
    for (int mi = 0; mi < 4; mi++) {
        int rowa = row0 + wm + mi * 16 + (lane >> 2);
#pragma unroll
        for (int ni = 0; ni < 4; ni++) {
            int c = col0 + wn + ni * 8 + (lane & 3) * 2;
            float b0v = be2[c], b1v = be2[c + 1];
            if (rowa < Ee) {
                *(__nv_bfloat162*)&g_We[(size_t)rowa * DDm + c] =
                    __float22bfloat162_rn(make_float2(acc[mi][ni][0] + b0v, acc[mi][ni][1] + b1v));
            }
            if (rowa + 8 < Ee) {
                *(__nv_bfloat162*)&g_We[(size_t)(rowa + 8) * DDm + c] =
                    __float22bfloat162_rn(make_float2(acc[mi][ni][2] + b0v, acc[mi][ni][3] + b1v));
            }
        }
    }
}

// ---------------- degree / segments ----------------
__global__ void k_zero_deg() {
    int i = blockIdx.x * blockDim.x + threadIdx.x;
    if (i < Nn) g_deg[i] = 0.0f;
}
__global__ void k_count(const int* __restrict__ ei) {
    int e = blockIdx.x * blockDim.x + threadIdx.x;
    if (e < Ee) atomicAdd(&g_deg[ei[Ee + e]], 1.0f);
}
__global__ void k_segstart(const int* __restrict__ batch) {
    int b = blockIdx.x * blockDim.x + threadIdx.x;
    if (b > Bb) return;
    int lo = 0, hi = Nn;
    while (lo < hi) {
        int mid = (lo + hi) >> 1;
        if (batch[mid] < b) lo = mid + 1; else hi = mid;
    }
    g_seg[b] = lo;
}

// ---------------- message + scatter ----------------
__global__ void k_zero_agg() {
    int i = blockIdx.x * blockDim.x + threadIdx.x;
    if (i < Nn * Dd) g_agg[i] = 0.0f;
}
__global__ void k_msg(const int* __restrict__ ei) {
    int w = threadIdx.x >> 5;
    int e = blockIdx.x * 8 + w;
    int lane = threadIdx.x & 31;
    __shared__ float ss[8][Dd];
    if (e >= Ee) return;
    int src = ei[e], dst = ei[Ee + e];
    ss[w][lane] = g_h[src * Dd + lane];
    ss[w][lane + 32] = g_h[src * Dd + 32 + lane];
    __syncwarp();
    const __nv_bfloat162* W = (const __nv_bfloat162*)(g_We + (size_t)e * DDm);
    float a0 = 0.f, a1 = 0.f;
#pragma unroll
    for (int i = 0; i < Dd; i++) {
        float si = ss[w][i];
        float2 wf = __bfloat1622float2(W[i * 32 + lane]);
        a0 += si * wf.x;
        a1 += si * wf.y;
    }
    atomicAdd(&g_agg[dst * Dd + 2 * lane], a0);
    atomicAdd(&g_agg[dst * Dd + 2 * lane + 1], a1);
}

// ---------------- GRU cell ----------------
__global__ void k_gru(const float* __restrict__ W_ih, const float* __restrict__ W_hh,
                      const float* __restrict__ b_ih, const float* __restrict__ b_hh,
                      const float* __restrict__ b_conv) {
    int n = blockIdx.x, t = threadIdx.x;
    __shared__ float sm[Dd], sh[Dd];
    float dg = fmaxf(g_deg[n], 1.0f);
    sm[t] = fmaxf(g_agg[n * Dd + t] / dg + b_conv[t], 0.0f);
    sh[t] = g_h[n * Dd + t];
    __syncthreads();
    float gir = b_ih[t], giz = b_ih[Dd + t], gin = b_ih[2 * Dd + t];
    float ghr = b_hh[t], ghz = b_hh[Dd + t], ghn = b_hh[2 * Dd + t];
    const float4* Wr = (const float4*)&W_ih[t * Dd];
    const float4* Wz = (const float4*)&W_ih[(Dd + t) * Dd];
    const float4* Wn = (const float4*)&W_ih[(2 * Dd + t) * Dd];
    const float4* Vr = (const float4*)&W_hh[t * Dd];
    const float4* Vz = (const float4*)&W_hh[(Dd + t) * Dd];
    const float4* Vn = (const float4*)&W_hh[(2 * Dd + t) * Dd];
#pragma unroll
    for (int q = 0; q < Dd / 4; q++) {
        float4 m4 = *(const float4*)&sm[q * 4];
        float4 h4 = *(const float4*)&sh[q * 4];
        float4 w;
        w = Wr[q]; gir += m4.x * w.x + m4.y * w.y + m4.z * w.z + m4.w * w.w;
        w = Wz[q]; giz += m4.x * w.x + m4.y * w.y + m4.z * w.z + m4.w * w.w;
        w = Wn[q]; gin += m4.x * w.x + m4.y * w.y + m4.z * w.z + m4.w * w.w;
        w = Vr[q]; ghr += h4.x * w.x + h4.y * w.y + h4.z * w.z + h4.w * w.w;
        w = Vz[q]; ghz += h4.x * w.x + h4.y * w.y + h4.z * w.z + h4.w * w.w;
        w = Vn[q]; ghn += h4.x * w.x + h4.y * w.y + h4.z * w.z + h4.w * w.w;
    }
    float r = sigf(gir + ghr);
    float z = sigf(giz + ghz);
    float nn = tanhf(gin + r * ghn);
    g_h[n * Dd + t] = (1.0f - z) * nn + z * sh[t];
}

// ---------------- Set2Set ----------------
__global__ void k_zero_s2s() {
    int i = blockIdx.x * blockDim.x + threadIdx.x;
    if (i < Bb * 128) g_qstar[i] = 0.0f;
    else if (i < Bb * 192) g_hl[i - Bb * 128] = 0.0f;
    else if (i < Bb * 256) g_cl[i - Bb * 192] = 0.0f;
}

__global__ void k_lstm(const float* __restrict__ W_ihl, const float* __restrict__ W_hhl,
                       const float* __restrict__ b_ihl, const float* __restrict__ b_hhl) {
    int b = blockIdx.x, t = threadIdx.x;
    __shared__ float sq[2 * Dd], shl[Dd];
    sq[t] = g_qstar[b * 2 * Dd + t];
    sq[Dd + t] = g_qstar[b * 2 * Dd + Dd + t];
    shl[t] = g_hl[b * Dd + t];
    __syncthreads();
    float gi = b_ihl[t] + b_hhl[t];
    float gf = b_ihl[Dd + t] + b_hhl[Dd + t];
    float gg = b_ihl[2 * Dd + t] + b_hhl[2 * Dd + t];
    float go = b_ihl[3 * Dd + t] + b_hhl[3 * Dd + t];
    const float4* Pi = (const float4*)&W_ihl[t * 128];
    const float4* Pf = (const float4*)&W_ihl[(Dd + t) * 128];
    const float4* Pg = (const float4*)&W_ihl[(2 * Dd + t) * 128];
    const float4* Po = (const float4*)&W_ihl[(3 * Dd + t) * 128];
#pragma unroll
    for (int q = 0; q < 32; q++) {
        float4 v = *(const float4*)&sq[q * 4];
        float4 w;
        w = Pi[q]; gi += v.x * w.x + v.y * w.y + v.z * w.z + v.w * w.w;
        w = Pf[q]; gf += v.x * w.x + v.y * w.y + v.z * w.z + v.w * w.w;
        w = Pg[q]; gg += v.x * w.x + v.y * w.y + v.z * w.z + v.w * w.w;
        w = Po[q]; go += v.x * w.x + v.y * w.y + v.z * w.z + v.w * w.w;
    }
    const float4* Hi = (const float4*)&W_hhl[t * Dd];
    const float4* Hf = (const float4*)&W_hhl[(Dd + t) * Dd];
    const float4* Hg = (const float4*)&W_hhl[(2 * Dd + t) * Dd];
    const float4* Ho = (const float4*)&W_hhl[(3 * Dd + t) * Dd];
#pragma unroll
    for (int q = 0; q < 16; q++) {
        float4 v = *(const float4*)&shl[q * 4];
        float4 w;
        w = Hi[q]; gi += v.x * w.x + v.y * w.y + v.z * w.z + v.w * w.w;
        w = Hf[q]; gf += v.x * w.x + v.y * w.y + v.z * w.z + v.w * w.w;
        w = Hg[q]; gg += v.x * w.x + v.y * w.y + v.z * w.z + v.w * w.w;
        w = Ho[q]; go += v.x * w.x + v.y * w.y + v.z * w.z + v.w * w.w;
    }
    float c = g_cl[b * Dd + t];
    c = sigf(gf) * c + sigf(gi) * tanhf(gg);
    float hl = sigf(go) * tanhf(c);
    g_cl[b * Dd + t] = c;
    g_hl[b * Dd + t] = hl;
}

__global__ void k_dot(const int* __restrict__ batch) {
    int w = threadIdx.x >> 5;
    int n = blockIdx.x * 8 + w;
    int lane = threadIdx.x & 31;
    if (n >= Nn) return;
    int b = batch[n];
    float v = g_h[n * Dd + lane] * g_hl[b * Dd + lane]
            + g_h[n * Dd + 32 + lane] * g_hl[b * Dd + 32 + lane];
#pragma unroll
    for (int off = 16; off > 0; off >>= 1) v += __shfl_down_sync(0xffffffff, v, off);
    if (lane == 0) g_e[n] = v;
}

__global__ void k_attn() {
    int b = blockIdx.x, t = threadIdx.x;
    int s = g_seg[b], en = g_seg[b + 1];
    __shared__ float red[Dd];
    float mx = -1e30f;
    for (int n = s + t; n < en; n += Dd) mx = fmaxf(mx, g_e[n]);
    red[t] = mx;
    __syncthreads();
    for (int o = 32; o > 0; o >>= 1) {
        if (t < o) red[t] = fmaxf(red[t], red[t + o]);
        __syncthreads();
    }
    float emax = red[0];
    float racc = 0.f, wsum = 0.f;
    for (int n = s; n < en; n++) {
        float wv = expf(g_e[n] - emax);
        wsum += wv;
        racc += wv * g_h[n * Dd + t];
    }
    float r = (en > s) ? (racc / wsum) : 0.0f;
    g_qstar[b * 2 * Dd + t] = g_hl[b * Dd + t];
    g_qstar[b * 2 * Dd + Dd + t] = r;
}

// ---------------- output MLP ----------------
__global__ void k_mlp(const float* __restrict__ W1, const float* __restrict__ b1,
                      const float* __restrict__ W2, const float* __restrict__ b2,
                      float* __restrict__ pred) {
    int b = blockIdx.x, t = threadIdx.x;
    __shared__ float sq[2 * Dd];
    __shared__ float red[Dd];
    sq[t] = g_qstar[b * 2 * Dd + t];
    sq[Dd + t] = g_qstar[b * 2 * Dd + Dd + t];
    __syncthreads();
    float acc = b1[t];
    const float4* Wp = (const float4*)&W1[t * 128];
#pragma unroll
    for (int q = 0; q < 32; q++) {
        float4 w = Wp[q];
        float4 v = *(const float4*)&sq[q * 4];
        acc += v.x * w.x + v.y * w.y + v.z * w.z + v.w * w.w;
    }
    float y = fmaxf(acc, 0.0f);
    red[t] = y * W2[t];
    __syncthreads();
    for (int o = 32; o > 0; o >>= 1) {
        if (t < o) red[t] += red[t + o];
        __syncthreads();
    }
    if (t == 0) pred[b] = red[0] + b2[0];
}

// ---------------- launch ----------------
extern "C" void kernel_launch(void* const* d_in, const int* in_sizes, int n_in,
                              void* d_out, int out_size) {
    const float* x      = (const float*)d_in[0];
    const float* ea     = (const float*)d_in[1];
    const int*   ei     = (const int*)d_in[2];
    const int*   batch  = (const int*)d_in[3];
    const float* W0     = (const float*)d_in[4];
    const float* b0     = (const float*)d_in[5];
    const float* We1    = (const float*)d_in[6];
    const float* be1    = (const float*)d_in[7];
    const float* We2    = (const float*)d_in[8];
    const float* be2    = (const float*)d_in[9];
    const float* b_conv = (const float*)d_in[10];
    const float* W_ih   = (const float*)d_in[11];
    const float* W_hh   = (const float*)d_in[12];
    const float* b_ih   = (const float*)d_in[13];
    const float* b_hh   = (const float*)d_in[14];
    const float* W_ihl  = (const float*)d_in[15];
    const float* W_hhl  = (const float*)d_in[16];
    const float* b_ihl  = (const float*)d_in[17];
    const float* b_hhl  = (const float*)d_in[18];
    const float* W1     = (const float*)d_in[19];
    const float* b1     = (const float*)d_in[20];
    const float* W2     = (const float*)d_in[21];
    const float* b2     = (const float*)d_in[22];
    float* pred = (float*)d_out;

    k_lin0<<<Nn, Dd>>>(x, W0, b0);
    k_edgeh<<<Ee, HE>>>(ea, We1, be1);
    k_cvtW<<<(DDm * HE + 255) / 256, 256>>>(We2);

    const int gemm_smem = 2 * 128 * SPAD * (int)sizeof(__nv_bfloat16);
    cudaFuncSetAttribute(k_gemm_tc, cudaFuncAttributeMaxDynamicSharedMemorySize, gemm_smem);
    dim3 gg((Ee + 127) / 128, DDm / 128);
    k_gemm_tc<<<gg, 256, gemm_smem>>>(be2);

    k_zero_deg<<<(Nn + 255) / 256, 256>>>();
    k_count<<<(Ee + 255) / 256, 256>>>(ei);
    k_segstart<<<(Bb + 1 + 127) / 128, 128>>>(batch);

    for (int it = 0; it < 3; it++) {
        k_zero_agg<<<(Nn * Dd + 255) / 256, 256>>>();
        k_msg<<<(Ee + 7) / 8, 256>>>(ei);
        k_gru<<<Nn, Dd>>>(W_ih, W_hh, b_ih, b_hh, b_conv);
    }

    k_zero_s2s<<<(Bb * 256 + 255) / 256, 256>>>();
    for (int it = 0; it < 3; it++) {
        k_lstm<<<Bb, Dd>>>(W_ihl, W_hhl, b_ihl, b_hhl);
        k_dot<<<(Nn + 7) / 8, 256>>>(batch);
        k_attn<<<Bb, Dd>>>();
    }
    k_mlp<<<Bb, Dd>>>(W1, b1, W2, b2, pred);
}

// round 4
// speedup vs baseline: 3.1025x; 2.3186x over previous
#include <cuda_runtime.h>
#include <cuda_bf16.h>
#include <math.h>
#include <stdint.h>

#define Nn 20000
#define Ee 40000
#define Bb 1000
#define Ff 32
#define Dd 64
#define HE 128
#define DDm 4096

// ---------------- scratch ----------------
__device__ float g_h[Nn * Dd];                       // node state
__device__ __nv_bfloat16 g_Hb[(size_t)Ee * HE];      // edge hidden bf16 [E,128]
__device__ __nv_bfloat16 g_Wb[DDm * HE];             // We2 bf16 [4096,128]
__device__ __nv_bfloat16 g_We[(size_t)Ee * DDm];     // edge weights bf16 (327MB)
__device__ float g_agg[Nn * Dd];
__device__ float g_deg[Nn];
__device__ float g_e[Nn];
__device__ float g_qstar[Bb * 2 * Dd];
__device__ float g_hl[Bb * Dd];
__device__ float g_cl[Bb * Dd];
__device__ int   g_seg[Bb + 1];

// transposed weights [k][row] for coalesced reads
__device__ float g_Wt0[Ff * Dd];        // 32 x 64
__device__ float g_Wti[Dd * 3 * Dd];    // 64 x 192
__device__ float g_Wth[Dd * 3 * Dd];    // 64 x 192
__device__ float g_Wtil[2 * Dd * 4 * Dd]; // 128 x 256
__device__ float g_Wthl[Dd * 4 * Dd];   // 64 x 256
__device__ float g_Wt1[2 * Dd * Dd];    // 128 x 64

__device__ __forceinline__ float sigf(float v) { return 1.0f / (1.0f + expf(-v)); }

// ---------------- transpose all weights (tiny) ----------------
__global__ void k_transpose(const float* __restrict__ W0, const float* __restrict__ W_ih,
                            const float* __restrict__ W_hh, const float* __restrict__ W_ihl,
                            const float* __restrict__ W_hhl, const float* __restrict__ W1) {
    int i = blockIdx.x * blockDim.x + threadIdx.x;
    // W0: 64x32
    if (i < 2048) { int r = i / 32, k = i % 32; g_Wt0[k * 64 + r] = W0[i]; return; }
    i -= 2048;
    // W_ih: 192x64
    if (i < 12288) { int r = i / 64, k = i % 64; g_Wti[k * 192 + r] = W_ih[i]; return; }
    i -= 12288;
    // W_hh: 192x64
    if (i < 12288) { int r = i / 64, k = i % 64; g_Wth[k * 192 + r] = W_hh[i]; return; }
    i -= 12288;
    // W_ihl: 256x128
    if (i < 32768) { int r = i / 128, k = i % 128; g_Wtil[k * 256 + r] = W_ihl[i]; return; }
    i -= 32768;
    // W_hhl: 256x64
    if (i < 16384) { int r = i / 64, k = i % 64; g_Wthl[k * 256 + r] = W_hhl[i]; return; }
    i -= 16384;
    // W1: 64x128
    if (i < 8192) { int r = i / 128, k = i % 128; g_Wt1[k * 64 + r] = W1[i]; return; }
}

// ---------------- lin0: h = relu(x @ W0^T + b0) ----------------
__global__ void k_lin0(const float* __restrict__ x, const float* __restrict__ b0) {
    int n = blockIdx.x, t = threadIdx.x;
    __shared__ float sx[Ff];
    if (t < Ff) sx[t] = x[n * Ff + t];
    __syncthreads();
    float acc = b0[t];
#pragma unroll 8
    for (int k = 0; k < Ff; k++) acc += sx[k] * g_Wt0[k * 64 + t];
    g_h[n * Dd + t] = fmaxf(acc, 0.0f);
}

// ---------------- edge hidden (bf16 out) ----------------
__global__ void k_edgeh(const float* __restrict__ ea, const float* __restrict__ We1,
                        const float* __restrict__ be1) {
    int e = blockIdx.x, k = threadIdx.x;
    __shared__ float sa[5];
    __shared__ float sW[HE * 5];
    __shared__ float sb[HE];
    if (k < 5) sa[k] = ea[e * 5 + k];
    sb[k] = be1[k];
#pragma unroll
    for (int q = 0; q < 5; q++) sW[q * HE + k] = We1[(q * HE + k)];  // linear copy
    __syncthreads();
    float acc = sb[k];
#pragma unroll
    for (int j = 0; j < 5; j++) acc += sa[j] * sW[k * 5 + j];
    g_Hb[(size_t)e * HE + k] = __float2bfloat16(fmaxf(acc, 0.0f));
}

// ---------------- We2 -> bf16 ----------------
__global__ void k_cvtW(const float* __restrict__ We2) {
    int i = blockIdx.x * blockDim.x + threadIdx.x;
    if (i < DDm * HE) g_Wb[i] = __float2bfloat16(We2[i]);
}

// ---------------- tensor-core GEMM: We = Hb @ Wb^T + be2 (bf16 out) ----------------
#define SPAD 136
__global__ void __launch_bounds__(256) k_gemm_tc(const float* __restrict__ be2) {
    extern __shared__ __nv_bfloat16 smem[];
    __nv_bfloat16* As = smem;                 // [128][SPAD]
    __nv_bfloat16* Bs = smem + 128 * SPAD;    // [128][SPAD]
    int row0 = blockIdx.x * 128;
    int col0 = blockIdx.y * 128;
    int tid = threadIdx.x;

    for (int idx = tid; idx < 2048; idx += 256) {
        int r = idx >> 4, c = (idx & 15) * 8;
        uint4 v = make_uint4(0u, 0u, 0u, 0u);
        if (row0 + r < Ee) v = *(const uint4*)&g_Hb[(size_t)(row0 + r) * HE + c];
        *(uint4*)&As[r * SPAD + c] = v;
        uint4 w = *(const uint4*)&g_Wb[(size_t)(col0 + r) * HE + c];
        *(uint4*)&Bs[r * SPAD + c] = w;
    }
    __syncthreads();

    int wid = tid >> 5, lane = tid & 31;
    int wm = (wid >> 2) * 64;
    int wn = (wid & 3) * 32;
    int q = lane >> 3, r8 = lane & 7;

    float acc[4][4][4];
#pragma unroll
    for (int i = 0; i < 4; i++)
#pragma unroll
        for (int j = 0; j < 4; j++)
#pragma unroll
            for (int c = 0; c < 4; c++) acc[i][j][c] = 0.0f;

#pragma unroll
    for (int k0 = 0; k0 < 128; k0 += 16) {
        uint32_t a[4][4];
        uint32_t b[4][2];
#pragma unroll
        for (int mi = 0; mi < 4; mi++) {
            int m = wm + mi * 16 + ((q & 1) * 8) + r8;
            int k = k0 + ((q >> 1) * 8);
            uint32_t addr = (uint32_t)__cvta_generic_to_shared(&As[m * SPAD + k]);
            asm volatile("ldmatrix.sync.aligned.m8n8.x4.shared.b16 {%0,%1,%2,%3}, [%4];"
                         : "=r"(a[mi][0]), "=r"(a[mi][1]), "=r"(a[mi][2]), "=r"(a[mi][3])
                         : "r"(addr));
        }
#pragma unroll
        for (int np = 0; np < 2; np++) {
            int n = wn + np * 16 + ((q >> 1) * 8) + r8;
            int k = k0 + ((q & 1) * 8);
            uint32_t addr = (uint32_t)__cvta_generic_to_shared(&Bs[n * SPAD + k]);
            asm volatile("ldmatrix.sync.aligned.m8n8.x4.shared.b16 {%0,%1,%2,%3}, [%4];"
                         : "=r"(b[np * 2][0]), "=r"(b[np * 2][1]),
                           "=r"(b[np * 2 + 1][0]), "=r"(b[np * 2 + 1][1])
                         : "r"(addr));
        }
#pragma unroll
        for (int mi = 0; mi < 4; mi++)
#pragma unroll
            for (int ni = 0; ni < 4; ni++) {
                asm volatile(
                    "mma.sync.aligned.m16n8k16.row.col.f32.bf16.bf16.f32 "
                    "{%0,%1,%2,%3}, {%4,%5,%6,%7}, {%8,%9}, {%0,%1,%2,%3};"
                    : "+f"(acc[mi][ni][0]), "+f"(acc[mi][ni][1]),
                      "+f"(acc[mi][ni][2]), "+f"(acc[mi][ni][3])
                    : "r"(a[mi][0]), "r"(a[mi][1]), "r"(a[mi][2]), "r"(a[mi][3]),
                      "r"(b[ni][0]), "r"(b[ni][1]));
            }
    }

#pragma unroll
    for (int mi = 0; mi < 4; mi++) {
        int rowa = row0 + wm + mi * 16 + (lane >> 2);
#pragma unroll
        for (int ni = 0; ni < 4; ni++) {
            int c = col0 + wn + ni * 8 + (lane & 3) * 2;
            float b0v = be2[c], b1v = be2[c + 1];
            if (rowa < Ee) {
                *(__nv_bfloat162*)&g_We[(size_t)rowa * DDm + c] =
                    __float22bfloat162_rn(make_float2(acc[mi][ni][0] + b0v, acc[mi][ni][1] + b1v));
            }
            if (rowa + 8 < Ee) {
                *(__nv_bfloat162*)&g_We[(size_t)(rowa + 8) * DDm + c] =
                    __float22bfloat162_rn(make_float2(acc[mi][ni][2] + b0v, acc[mi][ni][3] + b1v));
            }
        }
    }
}

// ---------------- degree / segments ----------------
__global__ void k_zero_deg() {
    int i = blockIdx.x * blockDim.x + threadIdx.x;
    if (i < Nn) g_deg[i] = 0.0f;
}
__global__ void k_count(const int* __restrict__ ei) {
    int e = blockIdx.x * blockDim.x + threadIdx.x;
    if (e < Ee) atomicAdd(&g_deg[ei[Ee + e]], 1.0f);
}
__global__ void k_segstart(const int* __restrict__ batch) {
    int b = blockIdx.x * blockDim.x + threadIdx.x;
    if (b > Bb) return;
    int lo = 0, hi = Nn;
    while (lo < hi) {
        int mid = (lo + hi) >> 1;
        if (batch[mid] < b) lo = mid + 1; else hi = mid;
    }
    g_seg[b] = lo;
}

// ---------------- message + scatter ----------------
__global__ void k_zero_agg() {
    int i = blockIdx.x * blockDim.x + threadIdx.x;
    if (i < Nn * Dd) g_agg[i] = 0.0f;
}
__global__ void k_msg(const int* __restrict__ ei) {
    int w = threadIdx.x >> 5;
    int e = blockIdx.x * 8 + w;
    int lane = threadIdx.x & 31;
    __shared__ float ss[8][Dd];
    if (e >= Ee) return;
    int src = ei[e], dst = ei[Ee + e];
    ss[w][lane] = g_h[src * Dd + lane];
    ss[w][lane + 32] = g_h[src * Dd + 32 + lane];
    __syncwarp();
    const __nv_bfloat162* W = (const __nv_bfloat162*)(g_We + (size_t)e * DDm);
    float a0 = 0.f, a1 = 0.f;
#pragma unroll
    for (int i = 0; i < Dd; i++) {
        float si = ss[w][i];
        float2 wf = __bfloat1622float2(W[i * 32 + lane]);
        a0 += si * wf.x;
        a1 += si * wf.y;
    }
    atomicAdd(&g_agg[dst * Dd + 2 * lane], a0);
    atomicAdd(&g_agg[dst * Dd + 2 * lane + 1], a1);
}

// ---------------- GRU cell (coalesced transposed weights) ----------------
__global__ void k_gru(const float* __restrict__ b_ih, const float* __restrict__ b_hh,
                      const float* __restrict__ b_conv) {
    int n = blockIdx.x, t = threadIdx.x;
    __shared__ float sm[Dd], sh[Dd];
    float dg = fmaxf(g_deg[n], 1.0f);
    sm[t] = fmaxf(g_agg[n * Dd + t] / dg + b_conv[t], 0.0f);
    sh[t] = g_h[n * Dd + t];
    __syncthreads();
    float gir = b_ih[t], giz = b_ih[Dd + t], gin = b_ih[2 * Dd + t];
    float ghr = b_hh[t], ghz = b_hh[Dd + t], ghn = b_hh[2 * Dd + t];
#pragma unroll 8
    for (int k = 0; k < Dd; k++) {
        float mk = sm[k], hk = sh[k];
        const float* wi = &g_Wti[k * 192];
        const float* wh = &g_Wth[k * 192];
        gir += mk * wi[t];
        giz += mk * wi[Dd + t];
        gin += mk * wi[2 * Dd + t];
        ghr += hk * wh[t];
        ghz += hk * wh[Dd + t];
        ghn += hk * wh[2 * Dd + t];
    }
    float r = sigf(gir + ghr);
    float z = sigf(giz + ghz);
    float nn = tanhf(gin + r * ghn);
    g_h[n * Dd + t] = (1.0f - z) * nn + z * sh[t];
}

// ---------------- Set2Set ----------------
__global__ void k_zero_s2s() {
    int i = blockIdx.x * blockDim.x + threadIdx.x;
    if (i < Bb * 128) g_qstar[i] = 0.0f;
    else if (i < Bb * 192) g_hl[i - Bb * 128] = 0.0f;
    else if (i < Bb * 256) g_cl[i - Bb * 192] = 0.0f;
}

__global__ void k_lstm(const float* __restrict__ b_ihl, const float* __restrict__ b_hhl) {
    int b = blockIdx.x, t = threadIdx.x;
    __shared__ float sq[2 * Dd], shl[Dd];
    sq[t] = g_qstar[b * 2 * Dd + t];
    sq[Dd + t] = g_qstar[b * 2 * Dd + Dd + t];
    shl[t] = g_hl[b * Dd + t];
    __syncthreads();
    float gi = b_ihl[t] + b_hhl[t];
    float gf = b_ihl[Dd + t] + b_hhl[Dd + t];
    float gg = b_ihl[2 * Dd + t] + b_hhl[2 * Dd + t];
    float go = b_ihl[3 * Dd + t] + b_hhl[3 * Dd + t];
#pragma unroll 8
    for (int k = 0; k < 2 * Dd; k++) {
        float v = sq[k];
        const float* w = &g_Wtil[k * 256];
        gi += v * w[t];
        gf += v * w[Dd + t];
        gg += v * w[2 * Dd + t];
        go += v * w[3 * Dd + t];
    }
#pragma unroll 8
    for (int k = 0; k < Dd; k++) {
        float v = shl[k];
        const float* w = &g_Wthl[k * 256];
        gi += v * w[t];
        gf += v * w[Dd + t];
        gg += v * w[2 * Dd + t];
        go += v * w[3 * Dd + t];
    }
    float c = g_cl[b * Dd + t];
    c = sigf(gf) * c + sigf(gi) * tanhf(gg);
    float hl = sigf(go) * tanhf(c);
    g_cl[b * Dd + t] = c;
    g_hl[b * Dd + t] = hl;
}

__global__ void k_dot(const int* __restrict__ batch) {
    int w = threadIdx.x >> 5;
    int n = blockIdx.x * 8 + w;
    int lane = threadIdx.x & 31;
    if (n >= Nn) return;
    int b = batch[n];
    float v = g_h[n * Dd + lane] * g_hl[b * Dd + lane]
            + g_h[n * Dd + 32 + lane] * g_hl[b * Dd + 32 + lane];
#pragma unroll
    for (int off = 16; off > 0; off >>= 1) v += __shfl_down_sync(0xffffffff, v, off);
    if (lane == 0) g_e[n] = v;
}

__global__ void k_attn() {
    int b = blockIdx.x, t = threadIdx.x;
    int s = g_seg[b], en = g_seg[b + 1];
    __shared__ float red[Dd];
    float mx = -1e30f;
    for (int n = s + t; n < en; n += Dd) mx = fmaxf(mx, g_e[n]);
    red[t] = mx;
    __syncthreads();
    for (int o = 32; o > 0; o >>= 1) {
        if (t < o) red[t] = fmaxf(red[t], red[t + o]);
        __syncthreads();
    }
    float emax = red[0];
    float racc = 0.f, wsum = 0.f;
    for (int n = s; n < en; n++) {
        float wv = expf(g_e[n] - emax);
        wsum += wv;
        racc += wv * g_h[n * Dd + t];
    }
    float r = (en > s) ? (racc / wsum) : 0.0f;
    g_qstar[b * 2 * Dd + t] = g_hl[b * Dd + t];
    g_qstar[b * 2 * Dd + Dd + t] = r;
}

// ---------------- output MLP ----------------
__global__ void k_mlp(const float* __restrict__ b1, const float* __restrict__ W2,
                      const float* __restrict__ b2, float* __restrict__ pred) {
    int b = blockIdx.x, t = threadIdx.x;
    __shared__ float sq[2 * Dd];
    __shared__ float red[Dd];
    sq[t] = g_qstar[b * 2 * Dd + t];
    sq[Dd + t] = g_qstar[b * 2 * Dd + Dd + t];
    __syncthreads();
    float acc = b1[t];
#pragma unroll 8
    for (int k = 0; k < 2 * Dd; k++) acc += sq[k] * g_Wt1[k * 64 + t];
    float y = fmaxf(acc, 0.0f);
    red[t] = y * W2[t];
    __syncthreads();
    for (int o = 32; o > 0; o >>= 1) {
        if (t < o) red[t] += red[t + o];
        __syncthreads();
    }
    if (t == 0) pred[b] = red[0] + b2[0];
}

// ---------------- launch ----------------
extern "C" void kernel_launch(void* const* d_in, const int* in_sizes, int n_in,
                              void* d_out, int out_size) {
    const float* x      = (const float*)d_in[0];
    const float* ea     = (const float*)d_in[1];
    const int*   ei     = (const int*)d_in[2];
    const int*   batch  = (const int*)d_in[3];
    const float* W0     = (const float*)d_in[4];
    const float* b0     = (const float*)d_in[5];
    const float* We1    = (const float*)d_in[6];
    const float* be1    = (const float*)d_in[7];
    const float* We2    = (const float*)d_in[8];
    const float* be2    = (const float*)d_in[9];
    const float* b_conv = (const float*)d_in[10];
    const float* W_ih   = (const float*)d_in[11];
    const float* W_hh   = (const float*)d_in[12];
    const float* b_ih   = (const float*)d_in[13];
    const float* b_hh   = (const float*)d_in[14];
    const float* W_ihl  = (const float*)d_in[15];
    const float* W_hhl  = (const float*)d_in[16];
    const float* b_ihl  = (const float*)d_in[17];
    const float* b_hhl  = (const float*)d_in[18];
    const float* W1     = (const float*)d_in[19];
    const float* b1     = (const float*)d_in[20];
    const float* W2     = (const float*)d_in[21];
    const float* b2     = (const float*)d_in[22];
    float* pred = (float*)d_out;

    k_transpose<<<(83968 + 255) / 256, 256>>>(W0, W_ih, W_hh, W_ihl, W_hhl, W1);
    k_lin0<<<Nn, Dd>>>(x, b0);
    k_edgeh<<<Ee, HE>>>(ea, We1, be1);
    k_cvtW<<<(DDm * HE + 255) / 256, 256>>>(We2);

    const int gemm_smem = 2 * 128 * SPAD * (int)sizeof(__nv_bfloat16);
    cudaFuncSetAttribute(k_gemm_tc, cudaFuncAttributeMaxDynamicSharedMemorySize, gemm_smem);
    dim3 gg((Ee + 127) / 128, DDm / 128);
    k_gemm_tc<<<gg, 256, gemm_smem>>>(be2);

    k_zero_deg<<<(Nn + 255) / 256, 256>>>();
    k_count<<<(Ee + 255) / 256, 256>>>(ei);
    k_segstart<<<(Bb + 1 + 127) / 128, 128>>>(batch);

    for (int it = 0; it < 3; it++) {
        k_zero_agg<<<(Nn * Dd + 255) / 256, 256>>>();
        k_msg<<<(Ee + 7) / 8, 256>>>(ei);
        k_gru<<<Nn, Dd>>>(b_ih, b_hh, b_conv);
    }

    k_zero_s2s<<<(Bb * 256 + 255) / 256, 256>>>();
    for (int it = 0; it < 3; it++) {
        k_lstm<<<Bb, Dd>>>(b_ihl, b_hhl);
        k_dot<<<(Nn + 7) / 8, 256>>>(batch);
        k_attn<<<Bb, Dd>>>();
    }
    k_mlp<<<Bb, Dd>>>(b1, W2, b2, pred);
}